// round 1
// baseline (speedup 1.0000x reference)
#include <cuda_runtime.h>
#include <math.h>

#define BATCH 32
#define SEQ   577
#define HEADS 12
#define HDIM  64
#define CDIM  768
#define MROWS (BATCH*SEQ)   // 18464

// Scratch (allocation-free rule: __device__ globals)
__device__ float g_Q[BATCH*HEADS*SEQ*HDIM];   // [B,H,N,D]
__device__ float g_K[BATCH*HEADS*SEQ*HDIM];
__device__ float g_V[BATCH*HEADS*SEQ*HDIM];
__device__ float g_attn[MROWS*CDIM];          // [B,N,C]

// ---------------------------------------------------------------------------
// GEMM 1: qkv = x @ W_qkv^T, scattered into Q/K/V in [B,H,N,D] layout.
// A: [M=18464, K=768] row-major, W: [2304, 768] row-major (both K-contiguous).
// 64x64 tile, BK=16, 256 threads, 4x4 micro-tile per thread.
// ---------------------------------------------------------------------------
__global__ __launch_bounds__(256) void qkv_gemm_kernel(const float* __restrict__ A,
                                                       const float* __restrict__ W) {
    __shared__ float As[16][64];   // transposed: As[k][m]
    __shared__ float Bs[16][64];   // transposed: Bs[k][n]
    const int tid = threadIdx.x;
    const int tx = tid & 15, ty = tid >> 4;
    const int mBase = blockIdx.y * 64;
    const int lr = tid >> 2;            // 0..63
    const int lk = (tid & 3) << 2;      // 0,4,8,12
    const int aRow = mBase + lr;
    const bool aValid = aRow < MROWS;
    const float* Ap = A + (long)aRow * CDIM + lk;
    const float* Wp = W + (long)(blockIdx.x * 64 + lr) * CDIM + lk;

    float acc[4][4] = {};
    for (int k0 = 0; k0 < CDIM; k0 += 16) {
        float4 a = aValid ? *(const float4*)(Ap + k0) : make_float4(0.f,0.f,0.f,0.f);
        float4 w = *(const float4*)(Wp + k0);
        As[lk+0][lr]=a.x; As[lk+1][lr]=a.y; As[lk+2][lr]=a.z; As[lk+3][lr]=a.w;
        Bs[lk+0][lr]=w.x; Bs[lk+1][lr]=w.y; Bs[lk+2][lr]=w.z; Bs[lk+3][lr]=w.w;
        __syncthreads();
        #pragma unroll
        for (int kk = 0; kk < 16; kk++) {
            float4 av = *(const float4*)(&As[kk][ty<<2]);
            float4 bv = *(const float4*)(&Bs[kk][tx<<2]);
            float aa[4] = {av.x, av.y, av.z, av.w};
            float bb[4] = {bv.x, bv.y, bv.z, bv.w};
            #pragma unroll
            for (int i = 0; i < 4; i++) {
                #pragma unroll
                for (int j = 0; j < 4; j++)
                    acc[i][j] = fmaf(aa[i], bb[j], acc[i][j]);
            }
        }
        __syncthreads();
    }
    // Epilogue: per-block column tile maps to a fixed (part, head).
    // n = blockIdx.x*64 + c, c<64  ->  part = blockIdx.x/12, head = blockIdx.x%12, d = c
    const int part = blockIdx.x / 12;
    const int hh   = blockIdx.x % 12;
    float* dst = (part == 0) ? g_Q : (part == 1) ? g_K : g_V;
    #pragma unroll
    for (int i = 0; i < 4; i++) {
        int m = mBase + (ty<<2) + i;
        if (m < MROWS) {
            int bb_ = m / SEQ, q = m - bb_ * SEQ;
            float* drow = dst + ((long)(bb_*HEADS + hh)*SEQ + q)*HDIM + (tx<<2);
            drow[0]=acc[i][0]; drow[1]=acc[i][1]; drow[2]=acc[i][2]; drow[3]=acc[i][3];
        }
    }
}

// ---------------------------------------------------------------------------
// Fused attention: per (b, h, q-tile of 64), flash-style online softmax over
// 10 key tiles of 64. All fp32. 256 threads, 4x4 micro-tiles.
// ---------------------------------------------------------------------------
__global__ __launch_bounds__(256) void attn_kernel_fn() {
    extern __shared__ float sm[];
    float* Qs = sm;            // [d][r]  4096 floats (pre-scaled by 1/8)
    float* Ks = sm + 4096;     // [d][c]  4096
    float* Vs = sm + 8192;     // [c][d]  4096 (natural layout)
    float* Ps = sm + 12288;    // [c][r]  stride 65 (pad kills bank conflicts)
    const int tid = threadIdx.x;
    const int tx = tid & 15, ty = tid >> 4;
    const int b = blockIdx.z, h = blockIdx.y;
    const int q0 = blockIdx.x * 64;
    const long base = (long)(b*HEADS + h) * SEQ * HDIM;
    const float* Qg = g_Q + base;
    const float* Kg = g_K + base;
    const float* Vg = g_V + base;

    #pragma unroll
    for (int t = 0; t < 4; t++) {
        int lin = tid + t*256;
        int r = lin >> 4;
        int d4 = (lin & 15) << 2;
        float4 v = make_float4(0.f,0.f,0.f,0.f);
        if (q0 + r < SEQ) v = *(const float4*)(Qg + (long)(q0+r)*HDIM + d4);
        Qs[(d4+0)*64 + r] = v.x * 0.125f;
        Qs[(d4+1)*64 + r] = v.y * 0.125f;
        Qs[(d4+2)*64 + r] = v.z * 0.125f;
        Qs[(d4+3)*64 + r] = v.w * 0.125f;
    }

    float o[4][4] = {};
    float mi[4] = {-1e30f,-1e30f,-1e30f,-1e30f};
    float li[4] = {0.f,0.f,0.f,0.f};

    for (int kt = 0; kt < 10; kt++) {
        const int c0 = kt * 64;
        int nk = SEQ - c0; if (nk > 64) nk = 64;
        __syncthreads();   // protect Vs/Ks from previous iteration's readers
        #pragma unroll
        for (int t = 0; t < 4; t++) {
            int lin = tid + t*256;
            int c = lin >> 4;
            int d4 = (lin & 15) << 2;
            float4 kv = make_float4(0.f,0.f,0.f,0.f);
            float4 vv = make_float4(0.f,0.f,0.f,0.f);
            if (c < nk) {
                kv = *(const float4*)(Kg + (long)(c0+c)*HDIM + d4);
                vv = *(const float4*)(Vg + (long)(c0+c)*HDIM + d4);
            }
            Ks[(d4+0)*64 + c] = kv.x;
            Ks[(d4+1)*64 + c] = kv.y;
            Ks[(d4+2)*64 + c] = kv.z;
            Ks[(d4+3)*64 + c] = kv.w;
            *(float4*)(Vs + c*64 + d4) = vv;
        }
        __syncthreads();

        // S = (Q*scale) @ K^T
        float s[4][4] = {};
        #pragma unroll 8
        for (int d = 0; d < 64; d++) {
            float4 qv = *(const float4*)(&Qs[d*64 + (ty<<2)]);
            float4 kv = *(const float4*)(&Ks[d*64 + (tx<<2)]);
            float qa[4]={qv.x,qv.y,qv.z,qv.w};
            float ka[4]={kv.x,kv.y,kv.z,kv.w};
            #pragma unroll
            for (int i=0;i<4;i++) {
                #pragma unroll
                for (int j=0;j<4;j++)
                    s[i][j] = fmaf(qa[i], ka[j], s[i][j]);
            }
        }
        if (nk < 64) {
            #pragma unroll
            for (int j=0;j<4;j++)
                if ((tx<<2)+j >= nk) { s[0][j]=-1e30f; s[1][j]=-1e30f; s[2][j]=-1e30f; s[3][j]=-1e30f; }
        }

        // Online softmax per row; row stats reduced across 16 same-ty lanes
        #pragma unroll
        for (int i=0;i<4;i++) {
            float rm = fmaxf(fmaxf(s[i][0], s[i][1]), fmaxf(s[i][2], s[i][3]));
            #pragma unroll
            for (int off = 8; off > 0; off >>= 1)
                rm = fmaxf(rm, __shfl_xor_sync(0xffffffffu, rm, off));
            float mnew = fmaxf(mi[i], rm);
            float corr = __expf(mi[i] - mnew);
            float p[4]; float rs = 0.f;
            #pragma unroll
            for (int j=0;j<4;j++) { p[j] = __expf(s[i][j] - mnew); rs += p[j]; }
            #pragma unroll
            for (int off = 8; off > 0; off >>= 1)
                rs += __shfl_xor_sync(0xffffffffu, rs, off);
            li[i] = li[i]*corr + rs;
            mi[i] = mnew;
            #pragma unroll
            for (int j=0;j<4;j++) o[i][j] *= corr;
            #pragma unroll
            for (int j=0;j<4;j++) Ps[((tx<<2)+j)*65 + (ty<<2)+i] = p[j];
        }
        __syncthreads();

        // O += P @ V
        #pragma unroll 8
        for (int kk = 0; kk < 64; kk++) {
            float4 vv = *(const float4*)(&Vs[kk*64 + (tx<<2)]);
            float va[4]={vv.x,vv.y,vv.z,vv.w};
            float pr[4];
            pr[0] = Ps[kk*65 + (ty<<2)+0];
            pr[1] = Ps[kk*65 + (ty<<2)+1];
            pr[2] = Ps[kk*65 + (ty<<2)+2];
            pr[3] = Ps[kk*65 + (ty<<2)+3];
            #pragma unroll
            for (int i=0;i<4;i++) {
                #pragma unroll
                for (int j=0;j<4;j++)
                    o[i][j] = fmaf(pr[i], va[j], o[i][j]);
            }
        }
    }

    // Epilogue: write [B,N,H*D] so proj GEMM reads contiguously
    #pragma unroll
    for (int i=0;i<4;i++) {
        int q = q0 + (ty<<2) + i;
        if (q < SEQ) {
            float inv = 1.0f / li[i];
            float* drow = g_attn + ((long)b*SEQ + q)*CDIM + h*HDIM + (tx<<2);
            drow[0]=o[i][0]*inv; drow[1]=o[i][1]*inv; drow[2]=o[i][2]*inv; drow[3]=o[i][3]*inv;
        }
    }
}

// ---------------------------------------------------------------------------
// GEMM 2: out = attn @ W_proj^T + b_proj
// ---------------------------------------------------------------------------
__global__ __launch_bounds__(256) void proj_gemm_kernel(const float* __restrict__ W,
                                                        const float* __restrict__ bias,
                                                        float* __restrict__ out) {
    __shared__ float As[16][64];
    __shared__ float Bs[16][64];
    const int tid = threadIdx.x;
    const int tx = tid & 15, ty = tid >> 4;
    const int mBase = blockIdx.y * 64;
    const int nBase = blockIdx.x * 64;
    const int lr = tid >> 2;
    const int lk = (tid & 3) << 2;
    const int aRow = mBase + lr;
    const bool aValid = aRow < MROWS;
    const float* Ap = g_attn + (long)aRow * CDIM + lk;
    const float* Wp = W + (long)(nBase + lr) * CDIM + lk;

    float acc[4][4] = {};
    for (int k0 = 0; k0 < CDIM; k0 += 16) {
        float4 a = aValid ? *(const float4*)(Ap + k0) : make_float4(0.f,0.f,0.f,0.f);
        float4 w = *(const float4*)(Wp + k0);
        As[lk+0][lr]=a.x; As[lk+1][lr]=a.y; As[lk+2][lr]=a.z; As[lk+3][lr]=a.w;
        Bs[lk+0][lr]=w.x; Bs[lk+1][lr]=w.y; Bs[lk+2][lr]=w.z; Bs[lk+3][lr]=w.w;
        __syncthreads();
        #pragma unroll
        for (int kk = 0; kk < 16; kk++) {
            float4 av = *(const float4*)(&As[kk][ty<<2]);
            float4 bv = *(const float4*)(&Bs[kk][tx<<2]);
            float aa[4] = {av.x, av.y, av.z, av.w};
            float bb[4] = {bv.x, bv.y, bv.z, bv.w};
            #pragma unroll
            for (int i = 0; i < 4; i++) {
                #pragma unroll
                for (int j = 0; j < 4; j++)
                    acc[i][j] = fmaf(aa[i], bb[j], acc[i][j]);
            }
        }
        __syncthreads();
    }
    #pragma unroll
    for (int i = 0; i < 4; i++) {
        int m = mBase + (ty<<2) + i;
        if (m < MROWS) {
            float* drow = out + (long)m * CDIM + nBase + (tx<<2);
            #pragma unroll
            for (int j = 0; j < 4; j++)
                drow[j] = acc[i][j] + bias[nBase + (tx<<2) + j];
        }
    }
}

extern "C" void kernel_launch(void* const* d_in, const int* in_sizes, int n_in,
                              void* d_out, int out_size) {
    const float* x     = (const float*)d_in[0];
    const float* Wqkv  = (const float*)d_in[1];
    const float* Wproj = (const float*)d_in[2];
    const float* bproj = (const float*)d_in[3];
    float* out = (float*)d_out;
    (void)in_sizes; (void)n_in; (void)out_size;

    // 65792 B dynamic smem for the attention kernel (3x 16KB tiles + padded P)
    cudaFuncSetAttribute(attn_kernel_fn, cudaFuncAttributeMaxDynamicSharedMemorySize, 65792);

    qkv_gemm_kernel<<<dim3(36, 289), 256>>>(x, Wqkv);                 // N=2304/64, M=ceil(18464/64)
    attn_kernel_fn<<<dim3(10, HEADS, BATCH), 256, 65792>>>();         // 10 q-tiles x 12 heads x 32 batch
    proj_gemm_kernel<<<dim3(12, 289), 256>>>(Wproj, bproj, out);      // N=768/64
}

// round 2
// speedup vs baseline: 1.0000x; 1.0000x over previous
#include <cuda_runtime.h>
#include <math.h>

#define BATCH 32
#define SEQ   577
#define HEADS 12
#define HDIM  64
#define CDIM  768
#define MROWS (BATCH*SEQ)   // 18464

// Scratch (allocation-free rule: __device__ globals)
__device__ float g_Q[BATCH*HEADS*SEQ*HDIM];   // [B,H,N,D]
__device__ float g_K[BATCH*HEADS*SEQ*HDIM];
__device__ float g_V[BATCH*HEADS*SEQ*HDIM];
__device__ float g_attn[MROWS*CDIM];          // [B,N,C]

// ---------------------------------------------------------------------------
// GEMM 1: qkv = x @ W_qkv^T, scattered into Q/K/V in [B,H,N,D] layout.
// A: [M=18464, K=768] row-major, W: [2304, 768] row-major (both K-contiguous).
// 64x64 tile, BK=16, 256 threads, 4x4 micro-tile per thread.
// ---------------------------------------------------------------------------
__global__ __launch_bounds__(256) void qkv_gemm_kernel(const float* __restrict__ A,
                                                       const float* __restrict__ W) {
    __shared__ float As[16][64];   // transposed: As[k][m]
    __shared__ float Bs[16][64];   // transposed: Bs[k][n]
    const int tid = threadIdx.x;
    const int tx = tid & 15, ty = tid >> 4;
    const int mBase = blockIdx.y * 64;
    const int lr = tid >> 2;            // 0..63
    const int lk = (tid & 3) << 2;      // 0,4,8,12
    const int aRow = mBase + lr;
    const bool aValid = aRow < MROWS;
    const float* Ap = A + (long)aRow * CDIM + lk;
    const float* Wp = W + (long)(blockIdx.x * 64 + lr) * CDIM + lk;

    float acc[4][4] = {};
    for (int k0 = 0; k0 < CDIM; k0 += 16) {
        float4 a = aValid ? *(const float4*)(Ap + k0) : make_float4(0.f,0.f,0.f,0.f);
        float4 w = *(const float4*)(Wp + k0);
        As[lk+0][lr]=a.x; As[lk+1][lr]=a.y; As[lk+2][lr]=a.z; As[lk+3][lr]=a.w;
        Bs[lk+0][lr]=w.x; Bs[lk+1][lr]=w.y; Bs[lk+2][lr]=w.z; Bs[lk+3][lr]=w.w;
        __syncthreads();
        #pragma unroll
        for (int kk = 0; kk < 16; kk++) {
            float4 av = *(const float4*)(&As[kk][ty<<2]);
            float4 bv = *(const float4*)(&Bs[kk][tx<<2]);
            float aa[4] = {av.x, av.y, av.z, av.w};
            float bb[4] = {bv.x, bv.y, bv.z, bv.w};
            #pragma unroll
            for (int i = 0; i < 4; i++) {
                #pragma unroll
                for (int j = 0; j < 4; j++)
                    acc[i][j] = fmaf(aa[i], bb[j], acc[i][j]);
            }
        }
        __syncthreads();
    }
    // Epilogue: per-block column tile maps to a fixed (part, head).
    // n = blockIdx.x*64 + c, c<64  ->  part = blockIdx.x/12, head = blockIdx.x%12, d = c
    const int part = blockIdx.x / 12;
    const int hh   = blockIdx.x % 12;
    float* dst = (part == 0) ? g_Q : (part == 1) ? g_K : g_V;
    #pragma unroll
    for (int i = 0; i < 4; i++) {
        int m = mBase + (ty<<2) + i;
        if (m < MROWS) {
            int bb_ = m / SEQ, q = m - bb_ * SEQ;
            float* drow = dst + ((long)(bb_*HEADS + hh)*SEQ + q)*HDIM + (tx<<2);
            drow[0]=acc[i][0]; drow[1]=acc[i][1]; drow[2]=acc[i][2]; drow[3]=acc[i][3];
        }
    }
}

// ---------------------------------------------------------------------------
// Fused attention: per (b, h, q-tile of 64), flash-style online softmax over
// 10 key tiles of 64. All fp32. 256 threads, 4x4 micro-tiles.
// ---------------------------------------------------------------------------
__global__ __launch_bounds__(256) void attn_kernel_fn() {
    extern __shared__ float sm[];
    float* Qs = sm;            // [d][r]  4096 floats (pre-scaled by 1/8)
    float* Ks = sm + 4096;     // [d][c]  4096
    float* Vs = sm + 8192;     // [c][d]  4096 (natural layout)
    float* Ps = sm + 12288;    // [c][r]  stride 65 (pad kills bank conflicts)
    const int tid = threadIdx.x;
    const int tx = tid & 15, ty = tid >> 4;
    const int b = blockIdx.z, h = blockIdx.y;
    const int q0 = blockIdx.x * 64;
    const long base = (long)(b*HEADS + h) * SEQ * HDIM;
    const float* Qg = g_Q + base;
    const float* Kg = g_K + base;
    const float* Vg = g_V + base;

    #pragma unroll
    for (int t = 0; t < 4; t++) {
        int lin = tid + t*256;
        int r = lin >> 4;
        int d4 = (lin & 15) << 2;
        float4 v = make_float4(0.f,0.f,0.f,0.f);
        if (q0 + r < SEQ) v = *(const float4*)(Qg + (long)(q0+r)*HDIM + d4);
        Qs[(d4+0)*64 + r] = v.x * 0.125f;
        Qs[(d4+1)*64 + r] = v.y * 0.125f;
        Qs[(d4+2)*64 + r] = v.z * 0.125f;
        Qs[(d4+3)*64 + r] = v.w * 0.125f;
    }

    float o[4][4] = {};
    float mi[4] = {-1e30f,-1e30f,-1e30f,-1e30f};
    float li[4] = {0.f,0.f,0.f,0.f};

    for (int kt = 0; kt < 10; kt++) {
        const int c0 = kt * 64;
        int nk = SEQ - c0; if (nk > 64) nk = 64;
        __syncthreads();   // protect Vs/Ks from previous iteration's readers
        #pragma unroll
        for (int t = 0; t < 4; t++) {
            int lin = tid + t*256;
            int c = lin >> 4;
            int d4 = (lin & 15) << 2;
            float4 kv = make_float4(0.f,0.f,0.f,0.f);
            float4 vv = make_float4(0.f,0.f,0.f,0.f);
            if (c < nk) {
                kv = *(const float4*)(Kg + (long)(c0+c)*HDIM + d4);
                vv = *(const float4*)(Vg + (long)(c0+c)*HDIM + d4);
            }
            Ks[(d4+0)*64 + c] = kv.x;
            Ks[(d4+1)*64 + c] = kv.y;
            Ks[(d4+2)*64 + c] = kv.z;
            Ks[(d4+3)*64 + c] = kv.w;
            *(float4*)(Vs + c*64 + d4) = vv;
        }
        __syncthreads();

        // S = (Q*scale) @ K^T
        float s[4][4] = {};
        #pragma unroll 8
        for (int d = 0; d < 64; d++) {
            float4 qv = *(const float4*)(&Qs[d*64 + (ty<<2)]);
            float4 kv = *(const float4*)(&Ks[d*64 + (tx<<2)]);
            float qa[4]={qv.x,qv.y,qv.z,qv.w};
            float ka[4]={kv.x,kv.y,kv.z,kv.w};
            #pragma unroll
            for (int i=0;i<4;i++) {
                #pragma unroll
                for (int j=0;j<4;j++)
                    s[i][j] = fmaf(qa[i], ka[j], s[i][j]);
            }
        }
        if (nk < 64) {
            #pragma unroll
            for (int j=0;j<4;j++)
                if ((tx<<2)+j >= nk) { s[0][j]=-1e30f; s[1][j]=-1e30f; s[2][j]=-1e30f; s[3][j]=-1e30f; }
        }

        // Online softmax per row; row stats reduced across 16 same-ty lanes
        #pragma unroll
        for (int i=0;i<4;i++) {
            float rm = fmaxf(fmaxf(s[i][0], s[i][1]), fmaxf(s[i][2], s[i][3]));
            #pragma unroll
            for (int off = 8; off > 0; off >>= 1)
                rm = fmaxf(rm, __shfl_xor_sync(0xffffffffu, rm, off));
            float mnew = fmaxf(mi[i], rm);
            float corr = __expf(mi[i] - mnew);
            float p[4]; float rs = 0.f;
            #pragma unroll
            for (int j=0;j<4;j++) { p[j] = __expf(s[i][j] - mnew); rs += p[j]; }
            #pragma unroll
            for (int off = 8; off > 0; off >>= 1)
                rs += __shfl_xor_sync(0xffffffffu, rs, off);
            li[i] = li[i]*corr + rs;
            mi[i] = mnew;
            #pragma unroll
            for (int j=0;j<4;j++) o[i][j] *= corr;
            #pragma unroll
            for (int j=0;j<4;j++) Ps[((tx<<2)+j)*65 + (ty<<2)+i] = p[j];
        }
        __syncthreads();

        // O += P @ V
        #pragma unroll 8
        for (int kk = 0; kk < 64; kk++) {
            float4 vv = *(const float4*)(&Vs[kk*64 + (tx<<2)]);
            float va[4]={vv.x,vv.y,vv.z,vv.w};
            float pr[4];
            pr[0] = Ps[kk*65 + (ty<<2)+0];
            pr[1] = Ps[kk*65 + (ty<<2)+1];
            pr[2] = Ps[kk*65 + (ty<<2)+2];
            pr[3] = Ps[kk*65 + (ty<<2)+3];
            #pragma unroll
            for (int i=0;i<4;i++) {
                #pragma unroll
                for (int j=0;j<4;j++)
                    o[i][j] = fmaf(pr[i], va[j], o[i][j]);
            }
        }
    }

    // Epilogue: write [B,N,H*D] so proj GEMM reads contiguously
    #pragma unroll
    for (int i=0;i<4;i++) {
        int q = q0 + (ty<<2) + i;
        if (q < SEQ) {
            float inv = 1.0f / li[i];
            float* drow = g_attn + ((long)b*SEQ + q)*CDIM + h*HDIM + (tx<<2);
            drow[0]=o[i][0]*inv; drow[1]=o[i][1]*inv; drow[2]=o[i][2]*inv; drow[3]=o[i][3]*inv;
        }
    }
}

// ---------------------------------------------------------------------------
// GEMM 2: out = attn @ W_proj^T + b_proj
// ---------------------------------------------------------------------------
__global__ __launch_bounds__(256) void proj_gemm_kernel(const float* __restrict__ W,
                                                        const float* __restrict__ bias,
                                                        float* __restrict__ out) {
    __shared__ float As[16][64];
    __shared__ float Bs[16][64];
    const int tid = threadIdx.x;
    const int tx = tid & 15, ty = tid >> 4;
    const int mBase = blockIdx.y * 64;
    const int nBase = blockIdx.x * 64;
    const int lr = tid >> 2;
    const int lk = (tid & 3) << 2;
    const int aRow = mBase + lr;
    const bool aValid = aRow < MROWS;
    const float* Ap = g_attn + (long)aRow * CDIM + lk;
    const float* Wp = W + (long)(nBase + lr) * CDIM + lk;

    float acc[4][4] = {};
    for (int k0 = 0; k0 < CDIM; k0 += 16) {
        float4 a = aValid ? *(const float4*)(Ap + k0) : make_float4(0.f,0.f,0.f,0.f);
        float4 w = *(const float4*)(Wp + k0);
        As[lk+0][lr]=a.x; As[lk+1][lr]=a.y; As[lk+2][lr]=a.z; As[lk+3][lr]=a.w;
        Bs[lk+0][lr]=w.x; Bs[lk+1][lr]=w.y; Bs[lk+2][lr]=w.z; Bs[lk+3][lr]=w.w;
        __syncthreads();
        #pragma unroll
        for (int kk = 0; kk < 16; kk++) {
            float4 av = *(const float4*)(&As[kk][ty<<2]);
            float4 bv = *(const float4*)(&Bs[kk][tx<<2]);
            float aa[4] = {av.x, av.y, av.z, av.w};
            float bb[4] = {bv.x, bv.y, bv.z, bv.w};
            #pragma unroll
            for (int i = 0; i < 4; i++) {
                #pragma unroll
                for (int j = 0; j < 4; j++)
                    acc[i][j] = fmaf(aa[i], bb[j], acc[i][j]);
            }
        }
        __syncthreads();
    }
    #pragma unroll
    for (int i = 0; i < 4; i++) {
        int m = mBase + (ty<<2) + i;
        if (m < MROWS) {
            float* drow = out + (long)m * CDIM + nBase + (tx<<2);
            #pragma unroll
            for (int j = 0; j < 4; j++)
                drow[j] = acc[i][j] + bias[nBase + (tx<<2) + j];
        }
    }
}

extern "C" void kernel_launch(void* const* d_in, const int* in_sizes, int n_in,
                              void* d_out, int out_size) {
    const float* x     = (const float*)d_in[0];
    const float* Wqkv  = (const float*)d_in[1];
    const float* Wproj = (const float*)d_in[2];
    const float* bproj = (const float*)d_in[3];
    float* out = (float*)d_out;
    (void)in_sizes; (void)n_in; (void)out_size;

    // 65792 B dynamic smem for the attention kernel (3x 16KB tiles + padded P)
    cudaFuncSetAttribute(attn_kernel_fn, cudaFuncAttributeMaxDynamicSharedMemorySize, 65792);

    qkv_gemm_kernel<<<dim3(36, 289), 256>>>(x, Wqkv);                 // N=2304/64, M=ceil(18464/64)
    attn_kernel_fn<<<dim3(10, HEADS, BATCH), 256, 65792>>>();         // 10 q-tiles x 12 heads x 32 batch
    proj_gemm_kernel<<<dim3(12, 289), 256>>>(Wproj, bproj, out);      // N=768/64
}

// round 3
// speedup vs baseline: 1.3405x; 1.3405x over previous
#include <cuda_runtime.h>

#define BATCH 32
#define SEQ   577
#define HEADS 12
#define HDIM  64
#define CDIM  768
#define MROWS (BATCH*SEQ)

__device__ float g_Q[BATCH*HEADS*SEQ*HDIM];
__device__ float g_K[BATCH*HEADS*SEQ*HDIM];
__device__ float g_V[BATCH*HEADS*SEQ*HDIM];
__device__ float g_attn[(size_t)MROWS*CDIM];

typedef unsigned long long u64t;

__device__ __forceinline__ void fma2(u64t& d, u64t a, u64t b) {
    asm("fma.rn.f32x2 %0, %1, %2, %0;" : "+l"(d) : "l"(a), "l"(b));
}
__device__ __forceinline__ void mul2(u64t& d, u64t a) {
    asm("mul.rn.f32x2 %0, %0, %1;" : "+l"(d) : "l"(a));
}
__device__ __forceinline__ u64t pack2(float lo, float hi) {
    u64t r; asm("mov.b64 %0, {%1, %2};" : "=l"(r) : "f"(lo), "f"(hi)); return r;
}
__device__ __forceinline__ u64t dup2(float x) { return pack2(x, x); }
__device__ __forceinline__ void unpack2(u64t p, float& lo, float& hi) {
    asm("mov.b64 {%0, %1}, %2;" : "=f"(lo), "=f"(hi) : "l"(p));
}
__device__ __forceinline__ void lds2(u64t& a, u64t& b, unsigned addr) {
    asm volatile("ld.shared.v2.u64 {%0, %1}, [%2];" : "=l"(a), "=l"(b) : "r"(addr));
}

// GEMM core: 128x128 tile, BK=16, 256 threads, 8x8 microtile, double buffer.
// A duplicated in smem (stride 260), B natural (stride 132).
#define GEMM_BUF_FLOATS 6272
#define GEMM_SMEM_BYTES (2*GEMM_BUF_FLOATS*4)

__device__ __forceinline__ void gemm_core(const float* __restrict__ A,
                                          const float* __restrict__ Wt,
                                          int mBase, int nBase,
                                          float* smf, u64t acc[8][4]) {
    const int tid = threadIdx.x;
    const int tx = tid & 15, ty = tid >> 4;
    const int ldRow = tid >> 1;
    const int ldK   = (tid & 1) * 8;
    const bool aValid = (mBase + ldRow) < MROWS;
    const float* Ap = A  + (size_t)(mBase + ldRow) * CDIM + ldK;
    const float* Wp = Wt + (size_t)(nBase + ldRow) * CDIM + ldK;
    const unsigned uSm = (unsigned)__cvta_generic_to_shared(smf);
    const float4 z4 = make_float4(0.f,0.f,0.f,0.f);

    {
        float4 a0 = aValid ? *(const float4*)(Ap)     : z4;
        float4 a1 = aValid ? *(const float4*)(Ap + 4) : z4;
        float4 b0 = *(const float4*)(Wp);
        float4 b1 = *(const float4*)(Wp + 4);
        float av[8] = {a0.x,a0.y,a0.z,a0.w,a1.x,a1.y,a1.z,a1.w};
        float bv[8] = {b0.x,b0.y,b0.z,b0.w,b1.x,b1.y,b1.z,b1.w};
        float* As = smf; float* Bs = smf + 4160;
        #pragma unroll
        for (int w = 0; w < 8; w++) {
            float* ap = As + (ldK + w)*260 + 2*ldRow;
            ap[0] = av[w]; ap[1] = av[w];
            Bs[(ldK + w)*132 + ldRow] = bv[w];
        }
    }
    __syncthreads();

    int buf = 0;
    for (int k0 = 0; k0 < CDIM; k0 += 16) {
        const bool more = (k0 + 16) < CDIM;
        float4 na0, na1, nb0, nb1;
        if (more) {
            na0 = aValid ? *(const float4*)(Ap + k0 + 16) : z4;
            na1 = aValid ? *(const float4*)(Ap + k0 + 20) : z4;
            nb0 = *(const float4*)(Wp + k0 + 16);
            nb1 = *(const float4*)(Wp + k0 + 20);
        }
        const unsigned aB = uSm + (unsigned)buf * (GEMM_BUF_FLOATS*4);
        const unsigned bB = aB + 4160*4;
        #pragma unroll
        for (int kk = 0; kk < 16; kk++) {
            u64t ad[8], bp[4];
            lds2(ad[0], ad[1], aB + (kk*260 + 8*ty)*4);
            lds2(ad[2], ad[3], aB + (kk*260 + 8*ty + 4)*4);
            lds2(ad[4], ad[5], aB + (kk*260 + 128 + 8*ty)*4);
            lds2(ad[6], ad[7], aB + (kk*260 + 128 + 8*ty + 4)*4);
            lds2(bp[0], bp[1], bB + (kk*132 + 4*tx)*4);
            lds2(bp[2], bp[3], bB + (kk*132 + 64 + 4*tx)*4);
            #pragma unroll
            for (int i = 0; i < 8; i++)
                #pragma unroll
                for (int jp = 0; jp < 4; jp++)
                    fma2(acc[i][jp], ad[i], bp[jp]);
        }
        if (more) {
            float* As = smf + (buf ^ 1)*GEMM_BUF_FLOATS;
            float* Bs = As + 4160;
            float av[8] = {na0.x,na0.y,na0.z,na0.w,na1.x,na1.y,na1.z,na1.w};
            float bv[8] = {nb0.x,nb0.y,nb0.z,nb0.w,nb1.x,nb1.y,nb1.z,nb1.w};
            #pragma unroll
            for (int w = 0; w < 8; w++) {
                float* ap = As + (ldK + w)*260 + 2*ldRow;
                ap[0] = av[w]; ap[1] = av[w];
                Bs[(ldK + w)*132 + ldRow] = bv[w];
            }
            __syncthreads();
            buf ^= 1;
        }
    }
}

__global__ __launch_bounds__(256, 2) void qkv_gemm_kernel(const float* __restrict__ A,
                                                          const float* __restrict__ W) {
    extern __shared__ float smf[];
    const int tx = threadIdx.x & 15, ty = threadIdx.x >> 4;
    const int mBase = blockIdx.y * 128;
    const int nBase = blockIdx.x * 128;
    u64t acc[8][4];
    #pragma unroll
    for (int i = 0; i < 8; i++)
        #pragma unroll
        for (int j = 0; j < 4; j++) acc[i][j] = 0ull;

    gemm_core(A, W, mBase, nBase, smf, acc);

    #pragma unroll
    for (int half = 0; half < 2; half++) {
        const int colBase = nBase + half*64 + 4*tx;
        const int part = colBase / CDIM;
        const int hh   = (colBase >> 6) % 12;
        float* dst = (part == 0) ? g_Q : (part == 1) ? g_K : g_V;
        #pragma unroll
        for (int i = 0; i < 8; i++) {
            const int row = (i < 4) ? (4*ty + i) : (64 + 4*ty + i - 4);
            const int m = mBase + row;
            if (m < MROWS) {
                float f0,f1,f2,f3;
                unpack2(acc[i][half*2+0], f0, f1);
                unpack2(acc[i][half*2+1], f2, f3);
                const int b = m / SEQ, q = m - b * SEQ;
                float* drow = dst + ((size_t)(b*HEADS + hh)*SEQ + q)*HDIM + (colBase & 63);
                *(float4*)drow = make_float4(f0,f1,f2,f3);
            }
        }
    }
}

__global__ __launch_bounds__(256, 2) void proj_gemm_kernel(const float* __restrict__ W,
                                                           const float* __restrict__ bias,
                                                           float* __restrict__ out) {
    extern __shared__ float smf[];
    const int tx = threadIdx.x & 15, ty = threadIdx.x >> 4;
    const int mBase = blockIdx.y * 128;
    const int nBase = blockIdx.x * 128;
    u64t acc[8][4];
    #pragma unroll
    for (int i = 0; i < 8; i++)
        #pragma unroll
        for (int j = 0; j < 4; j++) acc[i][j] = 0ull;

    gemm_core(g_attn, W, mBase, nBase, smf, acc);

    #pragma unroll
    for (int half = 0; half < 2; half++) {
        const int colBase = nBase + half*64 + 4*tx;
        const float4 bv = *(const float4*)(bias + colBase);
        #pragma unroll
        for (int i = 0; i < 8; i++) {
            const int row = (i < 4) ? (4*ty + i) : (64 + 4*ty + i - 4);
            const int m = mBase + row;
            if (m < MROWS) {
                float f0,f1,f2,f3;
                unpack2(acc[i][half*2+0], f0, f1);
                unpack2(acc[i][half*2+1], f2, f3);
                *(float4*)(out + (size_t)m*CDIM + colBase) =
                    make_float4(f0+bv.x, f1+bv.y, f2+bv.z, f3+bv.w);
            }
        }
    }
}

// Flash attention: 128-q x 64-k tiles, FFMA2, 256 threads.
#define ATTN_SMEM_BYTES (25600*4)

__global__ __launch_bounds__(256, 2) void attn_kernel_fn() {
    extern __shared__ float smf[];
    float* Qs = smf;            // [d][r] stride 132 (scaled)
    float* Ks = smf + 8448;     // [d][c] stride 68
    float* Vs = smf + 12800;    // [c][d] stride 68
    float* Pt = smf + 17152;    // [c][r] stride 132
    const unsigned uSm = (unsigned)__cvta_generic_to_shared(smf);
    const unsigned uQ = uSm, uP = uSm + 17152*4;

    const int tid = threadIdx.x;
    const int tx = tid & 15, ty = tid >> 4;
    const int b = blockIdx.z, h = blockIdx.y;
    const int q0 = blockIdx.x * 128;
    const size_t base = (size_t)(b*HEADS + h) * SEQ * HDIM;
    const float* Qg = g_Q + base;
    const float* Kg = g_K + base;
    const float* Vg = g_V + base;
    const float4 z4 = make_float4(0.f,0.f,0.f,0.f);

    #pragma unroll
    for (int t = 0; t < 8; t++) {
        int lin = t*256 + tid;
        int r = lin >> 4;
        int d4 = (lin & 15) << 2;
        float4 v = (q0 + r < SEQ) ? *(const float4*)(Qg + (size_t)(q0+r)*HDIM + d4) : z4;
        Qs[(d4+0)*132 + r] = v.x * 0.125f;
        Qs[(d4+1)*132 + r] = v.y * 0.125f;
        Qs[(d4+2)*132 + r] = v.z * 0.125f;
        Qs[(d4+3)*132 + r] = v.w * 0.125f;
    }

    u64t op[4][4];
    #pragma unroll
    for (int p = 0; p < 4; p++)
        #pragma unroll
        for (int j = 0; j < 4; j++) op[p][j] = 0ull;
    float mi[8], li[8];
    #pragma unroll
    for (int i = 0; i < 8; i++) { mi[i] = -1e30f; li[i] = 0.f; }

    for (int kt = 0; kt < 10; kt++) {
        const int c0 = kt * 64;
        int nk = SEQ - c0; if (nk > 64) nk = 64;
        __syncthreads();
        #pragma unroll
        for (int t = 0; t < 4; t++) {
            int lin = t*256 + tid;
            int c = lin >> 4;
            int d4 = (lin & 15) << 2;
            float4 kv = z4, vv = z4;
            if (c < nk) {
                kv = *(const float4*)(Kg + (size_t)(c0+c)*HDIM + d4);
                vv = *(const float4*)(Vg + (size_t)(c0+c)*HDIM + d4);
            }
            Ks[(d4+0)*68 + c] = kv.x;
            Ks[(d4+1)*68 + c] = kv.y;
            Ks[(d4+2)*68 + c] = kv.z;
            Ks[(d4+3)*68 + c] = kv.w;
            *(float4*)(Vs + c*68 + d4) = vv;
        }
        __syncthreads();

        u64t sp[4][4];
        #pragma unroll
        for (int p = 0; p < 4; p++)
            #pragma unroll
            for (int j = 0; j < 4; j++) sp[p][j] = 0ull;
        #pragma unroll 4
        for (int d = 0; d < 64; d++) {
            u64t qp[4];
            lds2(qp[0], qp[1], uQ + (d*132 + 4*ty)*4);
            lds2(qp[2], qp[3], uQ + (d*132 + 64 + 4*ty)*4);
            float4 kf = *(const float4*)(Ks + d*68 + 4*tx);
            u64t kd[4] = {dup2(kf.x), dup2(kf.y), dup2(kf.z), dup2(kf.w)};
            #pragma unroll
            for (int p = 0; p < 4; p++)
                #pragma unroll
                for (int j = 0; j < 4; j++)
                    fma2(sp[p][j], qp[p], kd[j]);
        }

        float s8[8][4];
        #pragma unroll
        for (int p = 0; p < 4; p++)
            #pragma unroll
            for (int j = 0; j < 4; j++)
                unpack2(sp[p][j], s8[2*p][j], s8[2*p+1][j]);
        if (nk < 64) {
            #pragma unroll
            for (int j = 0; j < 4; j++)
                if (4*tx + j >= nk) {
                    #pragma unroll
                    for (int i = 0; i < 8; i++) s8[i][j] = -1e30f;
                }
        }

        float corr[8];
        #pragma unroll
        for (int i = 0; i < 8; i++) {
            float rm = fmaxf(fmaxf(s8[i][0], s8[i][1]), fmaxf(s8[i][2], s8[i][3]));
            #pragma unroll
            for (int off = 8; off > 0; off >>= 1)
                rm = fmaxf(rm, __shfl_xor_sync(0xffffffffu, rm, off));
            float mnew = fmaxf(mi[i], rm);
            corr[i] = __expf(mi[i] - mnew);
            float rs = 0.f;
            #pragma unroll
            for (int j = 0; j < 4; j++) { s8[i][j] = __expf(s8[i][j] - mnew); rs += s8[i][j]; }
            #pragma unroll
            for (int off = 8; off > 0; off >>= 1)
                rs += __shfl_xor_sync(0xffffffffu, rs, off);
            li[i] = li[i]*corr[i] + rs;
            mi[i] = mnew;
        }
        #pragma unroll
        for (int p = 0; p < 4; p++) {
            u64t cp = pack2(corr[2*p], corr[2*p+1]);
            #pragma unroll
            for (int j = 0; j < 4; j++) mul2(op[p][j], cp);
        }
        #pragma unroll
        for (int j = 0; j < 4; j++) {
            *(float4*)(Pt + (4*tx+j)*132 + 4*ty) =
                make_float4(s8[0][j], s8[1][j], s8[2][j], s8[3][j]);
            *(float4*)(Pt + (4*tx+j)*132 + 64 + 4*ty) =
                make_float4(s8[4][j], s8[5][j], s8[6][j], s8[7][j]);
        }
        __syncthreads();

        #pragma unroll 4
        for (int kk = 0; kk < 64; kk++) {
            u64t pp[4];
            lds2(pp[0], pp[1], uP + (kk*132 + 4*ty)*4);
            lds2(pp[2], pp[3], uP + (kk*132 + 64 + 4*ty)*4);
            float4 vf = *(const float4*)(Vs + kk*68 + 4*tx);
            u64t vd[4] = {dup2(vf.x), dup2(vf.y), dup2(vf.z), dup2(vf.w)};
            #pragma unroll
            for (int p = 0; p < 4; p++)
                #pragma unroll
                for (int j = 0; j < 4; j++)
                    fma2(op[p][j], pp[p], vd[j]);
        }
    }

    float o8[8][4];
    #pragma unroll
    for (int p = 0; p < 4; p++)
        #pragma unroll
        for (int j = 0; j < 4; j++)
            unpack2(op[p][j], o8[2*p][j], o8[2*p+1][j]);
    #pragma unroll
    for (int i = 0; i < 8; i++) {
        const int row = (i < 4) ? (4*ty + i) : (64 + 4*ty + i - 4);
        const int q = q0 + row;
        if (q < SEQ) {
            float inv = 1.0f / li[i];
            float* drow = g_attn + ((size_t)b*SEQ + q)*CDIM + h*HDIM + 4*tx;
            *(float4*)drow = make_float4(o8[i][0]*inv, o8[i][1]*inv,
                                         o8[i][2]*inv, o8[i][3]*inv);
        }
    }
}

extern "C" void kernel_launch(void* const* d_in, const int* in_sizes, int n_in,
                              void* d_out, int out_size) {
    const float* x     = (const float*)d_in[0];
    const float* Wqkv  = (const float*)d_in[1];
    const float* Wproj = (const float*)d_in[2];
    const float* bproj = (const float*)d_in[3];
    float* out = (float*)d_out;
    (void)in_sizes; (void)n_in; (void)out_size;

    cudaFuncSetAttribute(qkv_gemm_kernel,  cudaFuncAttributeMaxDynamicSharedMemorySize, GEMM_SMEM_BYTES);
    cudaFuncSetAttribute(proj_gemm_kernel, cudaFuncAttributeMaxDynamicSharedMemorySize, GEMM_SMEM_BYTES);
    cudaFuncSetAttribute(attn_kernel_fn,   cudaFuncAttributeMaxDynamicSharedMemorySize, ATTN_SMEM_BYTES);

    qkv_gemm_kernel<<<dim3(18, 145), 256, GEMM_SMEM_BYTES>>>(x, Wqkv);
    attn_kernel_fn<<<dim3(5, HEADS, BATCH), 256, ATTN_SMEM_BYTES>>>();
    proj_gemm_kernel<<<dim3(6, 145), 256, GEMM_SMEM_BYTES>>>(Wproj, bproj, out);
}

// round 5
// speedup vs baseline: 2.3230x; 1.7329x over previous
#include <cuda_runtime.h>
#include <cuda_bf16.h>
#include <cstdint>

#define BATCH 32
#define SEQ   577
#define HEADS 12
#define HDIM  64
#define CDIM  768
#define MROWS (BATCH*SEQ)
#define QKVN  2304

__device__ float g_Q[(size_t)BATCH*HEADS*SEQ*HDIM];
__device__ float g_K[(size_t)BATCH*HEADS*SEQ*HDIM];
__device__ float g_V[(size_t)BATCH*HEADS*SEQ*HDIM];
__device__ __nv_bfloat16 g_xh[(size_t)MROWS*CDIM], g_xl[(size_t)MROWS*CDIM];
__device__ __nv_bfloat16 g_wqh[(size_t)QKVN*CDIM], g_wql[(size_t)QKVN*CDIM];
__device__ __nv_bfloat16 g_wph[(size_t)CDIM*CDIM], g_wpl[(size_t)CDIM*CDIM];
__device__ __nv_bfloat16 g_ah[(size_t)MROWS*CDIM], g_al[(size_t)MROWS*CDIM];

typedef unsigned long long u64t;

// ---------------- FFMA2 helpers (attention) ----------------
__device__ __forceinline__ void fma2(u64t& d, u64t a, u64t b) {
    asm("fma.rn.f32x2 %0, %1, %2, %0;" : "+l"(d) : "l"(a), "l"(b));
}
__device__ __forceinline__ void mul2(u64t& d, u64t a) {
    asm("mul.rn.f32x2 %0, %0, %1;" : "+l"(d) : "l"(a));
}
__device__ __forceinline__ u64t pack2(float lo, float hi) {
    u64t r; asm("mov.b64 %0, {%1, %2};" : "=l"(r) : "f"(lo), "f"(hi)); return r;
}
__device__ __forceinline__ u64t dup2(float x) { return pack2(x, x); }
__device__ __forceinline__ void unpack2(u64t p, float& lo, float& hi) {
    asm("mov.b64 {%0, %1}, %2;" : "=f"(lo), "=f"(hi) : "l"(p));
}
__device__ __forceinline__ void lds2(u64t& a, u64t& b, unsigned addr) {
    asm volatile("ld.shared.v2.u64 {%0, %1}, [%2];" : "=l"(a), "=l"(b) : "r"(addr));
}

// ---------------- HMMA helpers ----------------
__device__ __forceinline__ void ldsm4(uint32_t* r, uint32_t addr) {
    asm volatile("ldmatrix.sync.aligned.m8n8.x4.shared.b16 {%0,%1,%2,%3}, [%4];"
        : "=r"(r[0]), "=r"(r[1]), "=r"(r[2]), "=r"(r[3]) : "r"(addr));
}
__device__ __forceinline__ void mma_bf16(float* c, const uint32_t* a, const uint32_t* b) {
    asm volatile("mma.sync.aligned.m16n8k16.row.col.f32.bf16.bf16.f32 "
        "{%0,%1,%2,%3}, {%4,%5,%6,%7}, {%8,%9}, {%0,%1,%2,%3};"
        : "+f"(c[0]), "+f"(c[1]), "+f"(c[2]), "+f"(c[3])
        : "r"(a[0]), "r"(a[1]), "r"(a[2]), "r"(a[3]), "r"(b[0]), "r"(b[1]));
}

// ---------------- fp32 -> bf16 hi/lo split kernels ----------------
__device__ __forceinline__ void cvt_body(const float* __restrict__ s,
                                         __nv_bfloat16* __restrict__ hi,
                                         __nv_bfloat16* __restrict__ lo) {
    size_t i = ((size_t)blockIdx.x * 256 + threadIdx.x) * 4;
    float4 v = *(const float4*)(s + i);
    float f[4] = {v.x, v.y, v.z, v.w};
    __nv_bfloat16 h[4], l[4];
    #pragma unroll
    for (int j = 0; j < 4; j++) {
        h[j] = __float2bfloat16(f[j]);
        l[j] = __float2bfloat16(f[j] - __bfloat162float(h[j]));
    }
    *(__nv_bfloat162*)(hi + i)     = *(__nv_bfloat162*)&h[0];
    *(__nv_bfloat162*)(hi + i + 2) = *(__nv_bfloat162*)&h[2];
    *(__nv_bfloat162*)(lo + i)     = *(__nv_bfloat162*)&l[0];
    *(__nv_bfloat162*)(lo + i + 2) = *(__nv_bfloat162*)&l[2];
}
__global__ __launch_bounds__(256) void cvt_x_kernel(const float* __restrict__ s)  { cvt_body(s, g_xh, g_xl); }
__global__ __launch_bounds__(256) void cvt_wq_kernel(const float* __restrict__ s) { cvt_body(s, g_wqh, g_wql); }
__global__ __launch_bounds__(256) void cvt_wp_kernel(const float* __restrict__ s) { cvt_body(s, g_wph, g_wpl); }

// ---------------- HMMA GEMM core: 128x128 tile, BK=32, 8 warps (64x32 each)
// smem: 4 arrays [128 rows][80 B] (32 bf16 data + pad): Ah, Al, Bh, Bl
#define ROWB 80
#define OAH 0
#define OAL 10240
#define OBH 20480
#define OBL 30720
#define GEMM_SMEM 40960

__device__ __forceinline__ void mma_core(const __nv_bfloat16* __restrict__ Ah,
                                         const __nv_bfloat16* __restrict__ Al,
                                         const __nv_bfloat16* __restrict__ Bh,
                                         const __nv_bfloat16* __restrict__ Bl,
                                         int mBase, int nBase, float acc[4][4][4]) {
    extern __shared__ char smc[];
    const uint32_t su = (uint32_t)__cvta_generic_to_shared(smc);
    const int tid = threadIdx.x;
    const int lane = tid & 31, w = tid >> 5;
    const int wm = w & 1, wn = w >> 1;
    const int lrow = tid >> 1, lu = tid & 1;
    const bool aOk = (mBase + lrow) < MROWS;
    const __nv_bfloat16* pAh = Ah + (size_t)(mBase + lrow) * CDIM + lu * 16;
    const __nv_bfloat16* pAl = Al + (size_t)(mBase + lrow) * CDIM + lu * 16;
    const __nv_bfloat16* pBh = Bh + (size_t)(nBase + lrow) * CDIM + lu * 16;
    const __nv_bfloat16* pBl = Bl + (size_t)(nBase + lrow) * CDIM + lu * 16;
    const uint32_t stByte = (uint32_t)lrow * ROWB + (uint32_t)lu * 32;
    // ldmatrix lane addressing
    const uint32_t aRow = (uint32_t)(wm * 64 + (lane & 15));
    const uint32_t aKh  = (uint32_t)(lane >> 4);         // 0/1 -> k half
    const uint32_t bRow = (uint32_t)(wn * 32 + ((lane >> 4) << 3) + (lane & 7));
    const uint32_t bKh  = (uint32_t)((lane >> 3) & 1);
    const uint4 z = make_uint4(0, 0, 0, 0);

    for (int t = 0; t < 24; t++) {
        const int k0 = t * 32;
        uint4 vah0 = aOk ? *(const uint4*)(pAh + k0) : z;
        uint4 vah1 = aOk ? *(const uint4*)(pAh + k0 + 8) : z;
        uint4 val0 = aOk ? *(const uint4*)(pAl + k0) : z;
        uint4 val1 = aOk ? *(const uint4*)(pAl + k0 + 8) : z;
        uint4 vbh0 = *(const uint4*)(pBh + k0);
        uint4 vbh1 = *(const uint4*)(pBh + k0 + 8);
        uint4 vbl0 = *(const uint4*)(pBl + k0);
        uint4 vbl1 = *(const uint4*)(pBl + k0 + 8);
        __syncthreads();
        *(uint4*)(smc + OAH + stByte) = vah0; *(uint4*)(smc + OAH + stByte + 16) = vah1;
        *(uint4*)(smc + OAL + stByte) = val0; *(uint4*)(smc + OAL + stByte + 16) = val1;
        *(uint4*)(smc + OBH + stByte) = vbh0; *(uint4*)(smc + OBH + stByte + 16) = vbh1;
        *(uint4*)(smc + OBL + stByte) = vbl0; *(uint4*)(smc + OBL + stByte + 16) = vbl1;
        __syncthreads();
        #pragma unroll
        for (int ks = 0; ks < 2; ks++) {
            const uint32_t kOff = (uint32_t)ks * 32;
            uint32_t af[4][4], bhf[4][2], blf[4][2];
            #pragma unroll
            for (int i = 0; i < 4; i++)
                ldsm4(af[i], su + OAH + (aRow + i*16)*ROWB + kOff + aKh*16);
            #pragma unroll
            for (int j2 = 0; j2 < 2; j2++) {
                uint32_t r[4];
                ldsm4(r, su + OBH + (bRow + j2*16)*ROWB + kOff + bKh*16);
                bhf[2*j2][0]=r[0]; bhf[2*j2][1]=r[1]; bhf[2*j2+1][0]=r[2]; bhf[2*j2+1][1]=r[3];
                ldsm4(r, su + OBL + (bRow + j2*16)*ROWB + kOff + bKh*16);
                blf[2*j2][0]=r[0]; blf[2*j2][1]=r[1]; blf[2*j2+1][0]=r[2]; blf[2*j2+1][1]=r[3];
            }
            #pragma unroll
            for (int i = 0; i < 4; i++)
                #pragma unroll
                for (int j = 0; j < 4; j++)
                    mma_bf16(acc[i][j], af[i], bhf[j]);
            #pragma unroll
            for (int i = 0; i < 4; i++)
                #pragma unroll
                for (int j = 0; j < 4; j++)
                    mma_bf16(acc[i][j], af[i], blf[j]);
            #pragma unroll
            for (int i = 0; i < 4; i++)
                ldsm4(af[i], su + OAL + (aRow + i*16)*ROWB + kOff + aKh*16);
            #pragma unroll
            for (int i = 0; i < 4; i++)
                #pragma unroll
                for (int j = 0; j < 4; j++)
                    mma_bf16(acc[i][j], af[i], bhf[j]);
        }
    }
}

__global__ __launch_bounds__(256, 2) void qkv_mma_kernel() {
    const int mBase = blockIdx.y * 128, nBase = blockIdx.x * 128;
    float acc[4][4][4];
    #pragma unroll
    for (int i = 0; i < 4; i++)
        #pragma unroll
        for (int j = 0; j < 4; j++)
            #pragma unroll
            for (int c = 0; c < 4; c++) acc[i][j][c] = 0.f;
    mma_core(g_xh, g_xl, g_wqh, g_wql, mBase, nBase, acc);

    const int lane = threadIdx.x & 31, w = threadIdx.x >> 5;
    const int wm = w & 1, wn = w >> 1;
    const int part = nBase / CDIM;
    float* dstb = (part == 0) ? g_Q : (part == 1) ? g_K : g_V;
    const int nOff = nBase - part * CDIM;
    #pragma unroll
    for (int i = 0; i < 4; i++) {
        const int m0 = mBase + wm*64 + i*16 + (lane >> 2);
        #pragma unroll
        for (int j = 0; j < 4; j++) {
            const int ncol = nOff + wn*32 + j*8 + (lane & 3)*2;
            const int hd = ncol >> 6, d0 = ncol & 63;
            if (m0 < MROWS) {
                int b = m0 / SEQ, q = m0 - b * SEQ;
                *(float2*)(dstb + ((size_t)(b*HEADS + hd)*SEQ + q)*HDIM + d0) =
                    make_float2(acc[i][j][0], acc[i][j][1]);
            }
            const int m1 = m0 + 8;
            if (m1 < MROWS) {
                int b = m1 / SEQ, q = m1 - b * SEQ;
                *(float2*)(dstb + ((size_t)(b*HEADS + hd)*SEQ + q)*HDIM + d0) =
                    make_float2(acc[i][j][2], acc[i][j][3]);
            }
        }
    }
}

__global__ __launch_bounds__(256, 2) void proj_mma_kernel(float* __restrict__ out,
                                                          const float* __restrict__ bias) {
    const int mBase = blockIdx.y * 128, nBase = blockIdx.x * 128;
    float acc[4][4][4];
    #pragma unroll
    for (int i = 0; i < 4; i++)
        #pragma unroll
        for (int j = 0; j < 4; j++)
            #pragma unroll
            for (int c = 0; c < 4; c++) acc[i][j][c] = 0.f;
    mma_core(g_ah, g_al, g_wph, g_wpl, mBase, nBase, acc);

    const int lane = threadIdx.x & 31, w = threadIdx.x >> 5;
    const int wm = w & 1, wn = w >> 1;
    #pragma unroll
    for (int i = 0; i < 4; i++) {
        const int m0 = mBase + wm*64 + i*16 + (lane >> 2);
        #pragma unroll
        for (int j = 0; j < 4; j++) {
            const int ncol = nBase + wn*32 + j*8 + (lane & 3)*2;
            const float2 bv = *(const float2*)(bias + ncol);
            if (m0 < MROWS)
                *(float2*)(out + (size_t)m0*CDIM + ncol) =
                    make_float2(acc[i][j][0] + bv.x, acc[i][j][1] + bv.y);
            const int m1 = m0 + 8;
            if (m1 < MROWS)
                *(float2*)(out + (size_t)m1*CDIM + ncol) =
                    make_float2(acc[i][j][2] + bv.x, acc[i][j][3] + bv.y);
        }
    }
}

// ---------------- Flash attention (FFMA2), epilogue -> bf16 hi/lo ----------
#define ATTN_SMEM_BYTES (25600*4)

__global__ __launch_bounds__(256, 2) void attn_kernel_fn() {
    extern __shared__ float smf[];
    float* Qs = smf;            // [d][r] stride 132 (scaled)
    float* Ks = smf + 8448;     // [d][c] stride 68
    float* Vs = smf + 12800;    // [c][d] stride 68
    float* Pt = smf + 17152;    // [c][r] stride 132
    const unsigned uSm = (unsigned)__cvta_generic_to_shared(smf);
    const unsigned uQ = uSm, uP = uSm + 17152*4;

    const int tid = threadIdx.x;
    const int tx = tid & 15, ty = tid >> 4;
    const int b = blockIdx.z, h = blockIdx.y;
    const int q0 = blockIdx.x * 128;
    const size_t base = (size_t)(b*HEADS + h) * SEQ * HDIM;
    const float* Qg = g_Q + base;
    const float* Kg = g_K + base;
    const float* Vg = g_V + base;
    const float4 z4 = make_float4(0.f,0.f,0.f,0.f);

    #pragma unroll
    for (int t = 0; t < 8; t++) {
        int lin = t*256 + tid;
        int r = lin >> 4;
        int d4 = (lin & 15) << 2;
        float4 v = (q0 + r < SEQ) ? *(const float4*)(Qg + (size_t)(q0+r)*HDIM + d4) : z4;
        Qs[(d4+0)*132 + r] = v.x * 0.125f;
        Qs[(d4+1)*132 + r] = v.y * 0.125f;
        Qs[(d4+2)*132 + r] = v.z * 0.125f;
        Qs[(d4+3)*132 + r] = v.w * 0.125f;
    }

    u64t op[4][4];
    #pragma unroll
    for (int p = 0; p < 4; p++)
        #pragma unroll
        for (int j = 0; j < 4; j++) op[p][j] = 0ull;
    float mi[8], li[8];
    #pragma unroll
    for (int i = 0; i < 8; i++) { mi[i] = -1e30f; li[i] = 0.f; }

    for (int kt = 0; kt < 10; kt++) {
        const int c0 = kt * 64;
        int nk = SEQ - c0; if (nk > 64) nk = 64;
        __syncthreads();
        #pragma unroll
        for (int t = 0; t < 4; t++) {
            int lin = t*256 + tid;
            int c = lin >> 4;
            int d4 = (lin & 15) << 2;
            float4 kv = z4, vv = z4;
            if (c < nk) {
                kv = *(const float4*)(Kg + (size_t)(c0+c)*HDIM + d4);
                vv = *(const float4*)(Vg + (size_t)(c0+c)*HDIM + d4);
            }
            Ks[(d4+0)*68 + c] = kv.x;
            Ks[(d4+1)*68 + c] = kv.y;
            Ks[(d4+2)*68 + c] = kv.z;
            Ks[(d4+3)*68 + c] = kv.w;
            *(float4*)(Vs + c*68 + d4) = vv;
        }
        __syncthreads();

        u64t sp[4][4];
        #pragma unroll
        for (int p = 0; p < 4; p++)
            #pragma unroll
            for (int j = 0; j < 4; j++) sp[p][j] = 0ull;
        #pragma unroll 4
        for (int d = 0; d < 64; d++) {
            u64t qp[4];
            lds2(qp[0], qp[1], uQ + (d*132 + 4*ty)*4);
            lds2(qp[2], qp[3], uQ + (d*132 + 64 + 4*ty)*4);
            float4 kf = *(const float4*)(Ks + d*68 + 4*tx);
            u64t kd[4] = {dup2(kf.x), dup2(kf.y), dup2(kf.z), dup2(kf.w)};
            #pragma unroll
            for (int p = 0; p < 4; p++)
                #pragma unroll
                for (int j = 0; j < 4; j++)
                    fma2(sp[p][j], qp[p], kd[j]);
        }

        float s8[8][4];
        #pragma unroll
        for (int p = 0; p < 4; p++)
            #pragma unroll
            for (int j = 0; j < 4; j++)
                unpack2(sp[p][j], s8[2*p][j], s8[2*p+1][j]);
        if (nk < 64) {
            #pragma unroll
            for (int j = 0; j < 4; j++)
                if (4*tx + j >= nk) {
                    #pragma unroll
                    for (int i = 0; i < 8; i++) s8[i][j] = -1e30f;
                }
        }

        float corr[8];
        #pragma unroll
        for (int i = 0; i < 8; i++) {
            float rm = fmaxf(fmaxf(s8[i][0], s8[i][1]), fmaxf(s8[i][2], s8[i][3]));
            #pragma unroll
            for (int off = 8; off > 0; off >>= 1)
                rm = fmaxf(rm, __shfl_xor_sync(0xffffffffu, rm, off));
            float mnew = fmaxf(mi[i], rm);
            corr[i] = __expf(mi[i] - mnew);
            float rs = 0.f;
            #pragma unroll
            for (int j = 0; j < 4; j++) { s8[i][j] = __expf(s8[i][j] - mnew); rs += s8[i][j]; }
            #pragma unroll
            for (int off = 8; off > 0; off >>= 1)
                rs += __shfl_xor_sync(0xffffffffu, rs, off);
            li[i] = li[i]*corr[i] + rs;
            mi[i] = mnew;
        }
        #pragma unroll
        for (int p = 0; p < 4; p++) {
            u64t cp = pack2(corr[2*p], corr[2*p+1]);
            #pragma unroll
            for (int j = 0; j < 4; j++) mul2(op[p][j], cp);
        }
        #pragma unroll
        for (int j = 0; j < 4; j++) {
            *(float4*)(Pt + (4*tx+j)*132 + 4*ty) =
                make_float4(s8[0][j], s8[1][j], s8[2][j], s8[3][j]);
            *(float4*)(Pt + (4*tx+j)*132 + 64 + 4*ty) =
                make_float4(s8[4][j], s8[5][j], s8[6][j], s8[7][j]);
        }
        __syncthreads();

        #pragma unroll 4
        for (int kk = 0; kk < 64; kk++) {
            u64t pp[4];
            lds2(pp[0], pp[1], uP + (kk*132 + 4*ty)*4);
            lds2(pp[2], pp[3], uP + (kk*132 + 64 + 4*ty)*4);
            float4 vf = *(const float4*)(Vs + kk*68 + 4*tx);
            u64t vd[4] = {dup2(vf.x), dup2(vf.y), dup2(vf.z), dup2(vf.w)};
            #pragma unroll
            for (int p = 0; p < 4; p++)
                #pragma unroll
                for (int j = 0; j < 4; j++)
                    fma2(op[p][j], pp[p], vd[j]);
        }
    }

    float o8[8][4];
    #pragma unroll
    for (int p = 0; p < 4; p++)
        #pragma unroll
        for (int j = 0; j < 4; j++)
            unpack2(op[p][j], o8[2*p][j], o8[2*p+1][j]);
    #pragma unroll
    for (int i = 0; i < 8; i++) {
        const int row = (i < 4) ? (4*ty + i) : (64 + 4*ty + i - 4);
        const int q = q0 + row;
        if (q < SEQ) {
            float inv = 1.0f / li[i];
            size_t idx = ((size_t)b*SEQ + q)*CDIM + h*HDIM + 4*tx;
            __nv_bfloat16 hh[4], ll[4];
            #pragma unroll
            for (int j = 0; j < 4; j++) {
                float f = o8[i][j] * inv;
                hh[j] = __float2bfloat16(f);
                ll[j] = __float2bfloat16(f - __bfloat162float(hh[j]));
            }
            *(__nv_bfloat162*)(g_ah + idx)     = *(__nv_bfloat162*)&hh[0];
            *(__nv_bfloat162*)(g_ah + idx + 2) = *(__nv_bfloat162*)&hh[2];
            *(__nv_bfloat162*)(g_al + idx)     = *(__nv_bfloat162*)&ll[0];
            *(__nv_bfloat162*)(g_al + idx + 2) = *(__nv_bfloat162*)&ll[2];
        }
    }
}

extern "C" void kernel_launch(void* const* d_in, const int* in_sizes, int n_in,
                              void* d_out, int out_size) {
    const float* x     = (const float*)d_in[0];
    const float* Wqkv  = (const float*)d_in[1];
    const float* Wproj = (const float*)d_in[2];
    const float* bproj = (const float*)d_in[3];
    float* out = (float*)d_out;
    (void)in_sizes; (void)n_in; (void)out_size;

    cudaFuncSetAttribute(attn_kernel_fn, cudaFuncAttributeMaxDynamicSharedMemorySize, ATTN_SMEM_BYTES);

    cvt_x_kernel <<<13848, 256>>>(x);
    cvt_wq_kernel<<<1728,  256>>>(Wqkv);
    cvt_wp_kernel<<<576,   256>>>(Wproj);
    qkv_mma_kernel<<<dim3(18, 145), 256, GEMM_SMEM>>>();
    attn_kernel_fn<<<dim3(5, HEADS, BATCH), 256, ATTN_SMEM_BYTES>>>();
    proj_mma_kernel<<<dim3(6, 145), 256, GEMM_SMEM>>>(out, bproj);
}